// round 13
// baseline (speedup 1.0000x reference)
#include <cuda_runtime.h>
#include <cuda_fp16.h>
#include <math_constants.h>
#include <cstdint>

#define BATCH 4
#define SEQ   2048
#define EMB   1024
#define ADIM  1024
#define BSEQ  (BATCH * SEQ)

// int8 quantization constants: v = (h + l/256) * S1, |v| <= 4.5
#define QS1     (4.5f / 127.0f)
#define QINV1   (127.0f / 4.5f)
#define QINV2   (256.0f * 127.0f / 4.5f)

// ---------------------------------------------------------------------------
// Scratch (__device__ globals per allocation-free rule)
// ---------------------------------------------------------------------------
__device__ __align__(16) __half g_Xhi[BSEQ * EMB];
__device__ __align__(16) __half g_Xlo[BSEQ * EMB];
__device__ __align__(16) __half g_W  [3 * ADIM * EMB];
__device__ __align__(16) char   g_Qh8[BSEQ * ADIM];
__device__ __align__(16) char   g_Ql8[BSEQ * ADIM];
__device__ __align__(16) char   g_Kh8[BSEQ * ADIM];
__device__ __align__(16) char   g_Kl8[BSEQ * ADIM];
__device__ __align__(16) __half g_Vt [BATCH * ADIM * SEQ];   // V^T [b][a][s]
__device__ __align__(16) float  g_P  [(size_t)BATCH * SEQ * SEQ];
__device__ __align__(16) __half g_Phi[(size_t)BATCH * SEQ * SEQ];

// ---------------------------------------------------------------------------
// PTX helpers (sm_90-safe subset: mma.sync / ldmatrix / cp.async)
// ---------------------------------------------------------------------------
__device__ __forceinline__ uint32_t smem_to_u32(const void* p) {
    uint32_t a;
    asm("{ .reg .u64 t; cvta.to.shared.u64 t, %1; cvt.u32.u64 %0, t; }"
        : "=r"(a) : "l"(p));
    return a;
}

__device__ __forceinline__ void cp16(uint32_t dst, const void* src) {
    asm volatile("cp.async.cg.shared.global [%0], [%1], 16;"
                 :: "r"(dst), "l"(src) : "memory");
}

__device__ __forceinline__ void ldsm_x4(uint32_t (&r)[4], uint32_t addr) {
    asm volatile("ldmatrix.sync.aligned.m8n8.x4.shared.b16 {%0,%1,%2,%3}, [%4];"
                 : "=r"(r[0]), "=r"(r[1]), "=r"(r[2]), "=r"(r[3]) : "r"(addr));
}

__device__ __forceinline__ void mma_f16(float (&c)[4], const uint32_t (&a)[4],
                                        const uint32_t* b) {
    asm volatile(
        "mma.sync.aligned.m16n8k16.row.col.f32.f16.f16.f32 "
        "{%0,%1,%2,%3}, {%4,%5,%6,%7}, {%8,%9}, {%0,%1,%2,%3};"
        : "+f"(c[0]), "+f"(c[1]), "+f"(c[2]), "+f"(c[3])
        : "r"(a[0]), "r"(a[1]), "r"(a[2]), "r"(a[3]), "r"(b[0]), "r"(b[1]));
}

__device__ __forceinline__ void mma_s8(int (&c)[4], const uint32_t (&a)[4],
                                       const uint32_t* b) {
    asm volatile(
        "mma.sync.aligned.m16n8k32.row.col.s32.s8.s8.s32 "
        "{%0,%1,%2,%3}, {%4,%5,%6,%7}, {%8,%9}, {%0,%1,%2,%3};"
        : "+r"(c[0]), "+r"(c[1]), "+r"(c[2]), "+r"(c[3])
        : "r"(a[0]), "r"(a[1]), "r"(a[2]), "r"(a[3]), "r"(b[0]), "r"(b[1]));
}

// ---------------------------------------------------------------------------
// fp16 GEMM core (qkv / av): CTA 128 x CTAN, K-chunk 64, 256 thr, TERMS A copies
// ---------------------------------------------------------------------------
#define A_TILE     16384
#define SMEM_BYTES 196608
#define AV_SMEM    98304
#define RST        264            // fp16 staging stride (halfs)
#define TST        136            // transpose staging stride (halfs)
#define QROW       272            // int8 staging row stride (bytes), 16-aligned

__device__ __forceinline__ uint32_t sw128(uint32_t off) {
    return off ^ ((off >> 3) & 0x70);
}

template <int CTAN, int TERMS>
__device__ __forceinline__ void prefetch_chunk(
    uint32_t smem_u32, int stage, int kt,
    const __half* __restrict__ a_hi, const __half* __restrict__ a_lo, int lda,
    const __half* __restrict__ b, int ldb, int tid)
{
    constexpr int BOFF  = TERMS * A_TILE;
    constexpr int STAGE = BOFF + CTAN * 128;
    const uint32_t sbase = smem_u32 + stage * STAGE;
    #pragma unroll
    for (int arr = 0; arr < TERMS; ++arr) {
        const __half* src = arr == 0 ? a_hi : a_lo;
        const uint32_t tbase = sbase + arr * A_TILE;
        #pragma unroll
        for (int ii = 0; ii < 4; ++ii) {
            const int rem = ii * 256 + tid;
            const int row = rem >> 3, seg = rem & 7;
            cp16(tbase + sw128((uint32_t)(row * 128 + seg * 16)),
                 src + (size_t)row * lda + kt + seg * 8);
        }
    }
    #pragma unroll
    for (int ii = 0; ii < CTAN / 32; ++ii) {
        const int rem = ii * 256 + tid;
        const int row = rem >> 3, seg = rem & 7;
        cp16(sbase + BOFF + sw128((uint32_t)(row * 128 + seg * 16)),
             b + (size_t)row * ldb + kt + seg * 8);
    }
    asm volatile("cp.async.commit_group;" ::: "memory");
}

template <int CTAN, int TERMS>
__device__ __forceinline__ void compute_chunk(
    uint32_t smem_u32, int stage, int wm, int wn, int lane,
    float acc[4][CTAN / 32][4])
{
    constexpr int BOFF  = TERMS * A_TILE;
    constexpr int STAGE = BOFF + CTAN * 128;
    constexpr int NT = CTAN / 32;
    const uint32_t st = smem_u32 + stage * STAGE;
    #pragma unroll
    for (int ks = 0; ks < 4; ++ks) {
        uint32_t ah[4][4], al[4][4], bh[NT / 2][4];
        #pragma unroll
        for (int mt = 0; mt < 4; ++mt) {
            const int row = wm + mt * 16 + (lane & 15);
            const int byt = ks * 32 + ((lane >> 4) << 4);
            const uint32_t sw = sw128((uint32_t)(row * 128 + byt));
            ldsm_x4(ah[mt], st + sw);
            if constexpr (TERMS == 2) ldsm_x4(al[mt], st + A_TILE + sw);
        }
        #pragma unroll
        for (int p = 0; p < NT / 2; ++p) {
            const int row = wn + p * 16 + ((lane >> 4) << 3) + (lane & 7);
            const int byt = ks * 32 + (((lane >> 3) & 1) << 4);
            ldsm_x4(bh[p], st + BOFF + sw128((uint32_t)(row * 128 + byt)));
        }
        #pragma unroll
        for (int mt = 0; mt < 4; ++mt)
            #pragma unroll
            for (int nt = 0; nt < NT; ++nt)
                mma_f16(acc[mt][nt], ah[mt], &bh[nt >> 1][(nt & 1) * 2]);
        if constexpr (TERMS == 2) {
            #pragma unroll
            for (int mt = 0; mt < 4; ++mt)
                #pragma unroll
                for (int nt = 0; nt < NT; ++nt)
                    mma_f16(acc[mt][nt], al[mt], &bh[nt >> 1][(nt & 1) * 2]);
        }
    }
}

template <int CTAN, int TERMS>
__device__ __forceinline__ void mma_mainloop(
    uint32_t smem_u32,
    const __half* __restrict__ a_hi, const __half* __restrict__ a_lo, int lda,
    const __half* __restrict__ b, int ldb, int klen, float acc[4][CTAN / 32][4])
{
    const int tid = threadIdx.x;
    const int lane = tid & 31, w = tid >> 5;
    const int wm = (w & 1) * 64, wn = (w >> 1) * (CTAN / 4);
    const int nch = klen >> 6;

    prefetch_chunk<CTAN, TERMS>(smem_u32, 0, 0, a_hi, a_lo, lda, b, ldb, tid);

    int st = 0, nst = 1;
    for (int ch = 0; ch < nch; ++ch) {
        if (ch + 1 < nch) {
            prefetch_chunk<CTAN, TERMS>(smem_u32, nst, (ch + 1) << 6,
                                        a_hi, a_lo, lda, b, ldb, tid);
            asm volatile("cp.async.wait_group 1;" ::: "memory");
        } else {
            asm volatile("cp.async.wait_group 0;" ::: "memory");
        }
        __syncthreads();
        compute_chunk<CTAN, TERMS>(smem_u32, st, wm, wn, lane, acc);
        st = nst; nst = nst + 1 == 3 ? 0 : nst + 1;
    }
    __syncthreads();
}

// ---------------------------------------------------------------------------
// int8 GEMM core for scores: CTA 128x128, K-chunk 128 BYTES, 256 threads.
// 4 operand tiles per stage (qh, ql, kh, kl), each 128 rows x 128B, SW128.
// Stage = 64 KB, 3 stages.  Warp grid 2x4, warp tile 64x32.
// ---------------------------------------------------------------------------
#define S8_STAGE 65536

__device__ __forceinline__ void prefetch_s8(
    uint32_t smem_u32, int stage, int kt,
    const char* __restrict__ qh, const char* __restrict__ ql,
    const char* __restrict__ kh, const char* __restrict__ kl, int tid)
{
    const uint32_t sbase = smem_u32 + stage * S8_STAGE;
    #pragma unroll
    for (int arr = 0; arr < 4; ++arr) {
        const char* src = arr == 0 ? qh : arr == 1 ? ql : arr == 2 ? kh : kl;
        const uint32_t tbase = sbase + arr * 16384;
        #pragma unroll
        for (int ii = 0; ii < 4; ++ii) {
            const int rem = ii * 256 + tid;            // [0, 1024)
            const int row = rem >> 3, seg = rem & 7;
            cp16(tbase + sw128((uint32_t)(row * 128 + seg * 16)),
                 src + (size_t)row * ADIM + kt + seg * 16);
        }
    }
    asm volatile("cp.async.commit_group;" ::: "memory");
}

__device__ __forceinline__ void compute_s8(
    uint32_t smem_u32, int stage, int wm, int wn, int lane,
    int hh[4][4][4], int mid[4][4][4])
{
    const uint32_t st = smem_u32 + stage * S8_STAGE;
    #pragma unroll
    for (int ks = 0; ks < 4; ++ks) {                   // 4 x k32 per chunk
        uint32_t ah[4][4], al[4][4], bh[2][4], bl[2][4];
        #pragma unroll
        for (int mt = 0; mt < 4; ++mt) {
            const int row = wm + mt * 16 + (lane & 15);
            const int byt = ks * 32 + ((lane >> 4) << 4);
            const uint32_t sw = sw128((uint32_t)(row * 128 + byt));
            ldsm_x4(ah[mt], st + sw);
            ldsm_x4(al[mt], st + 16384 + sw);
        }
        #pragma unroll
        for (int p = 0; p < 2; ++p) {
            const int row = wn + p * 16 + ((lane >> 4) << 3) + (lane & 7);
            const int byt = ks * 32 + (((lane >> 3) & 1) << 4);
            const uint32_t sw = sw128((uint32_t)(row * 128 + byt));
            ldsm_x4(bh[p], st + 32768 + sw);
            ldsm_x4(bl[p], st + 49152 + sw);
        }
        #pragma unroll
        for (int mt = 0; mt < 4; ++mt)
            #pragma unroll
            for (int nt = 0; nt < 4; ++nt)
                mma_s8(hh[mt][nt], ah[mt], &bh[nt >> 1][(nt & 1) * 2]);
        #pragma unroll
        for (int mt = 0; mt < 4; ++mt)
            #pragma unroll
            for (int nt = 0; nt < 4; ++nt)
                mma_s8(mid[mt][nt], ah[mt], &bl[nt >> 1][(nt & 1) * 2]);
        #pragma unroll
        for (int mt = 0; mt < 4; ++mt)
            #pragma unroll
            for (int nt = 0; nt < 4; ++nt)
                mma_s8(mid[mt][nt], al[mt], &bh[nt >> 1][(nt & 1) * 2]);
    }
}

// ---------------------------------------------------------------------------
// Splits: X -> fp16 hi/lo;  W -> fp16 single
// ---------------------------------------------------------------------------
__global__ __launch_bounds__(256) void k_splitX(const float* __restrict__ src) {
    const int i = (blockIdx.x * 256 + threadIdx.x) * 4;
    float4 v = *(const float4*)(src + i);
    float vv[4] = {v.x, v.y, v.z, v.w};
    __half h[4], l[4];
    #pragma unroll
    for (int j = 0; j < 4; ++j) {
        h[j] = __float2half_rn(vv[j]);
        l[j] = __float2half_rn(vv[j] - __half2float(h[j]));
    }
    __half2 h01, h23, l01, l23;
    h01.x = h[0]; h01.y = h[1]; h23.x = h[2]; h23.y = h[3];
    l01.x = l[0]; l01.y = l[1]; l23.x = l[2]; l23.y = l[3];
    *(__half2*)(g_Xhi + i)     = h01;
    *(__half2*)(g_Xhi + i + 2) = h23;
    *(__half2*)(g_Xlo + i)     = l01;
    *(__half2*)(g_Xlo + i + 2) = l23;
}

__global__ __launch_bounds__(256) void k_splitW(const float* __restrict__ w0,
                                                const float* __restrict__ w1,
                                                const float* __restrict__ w2) {
    const int z = blockIdx.y;
    const float* src = z == 0 ? w0 : z == 1 ? w1 : w2;
    __half* dst = g_W + (size_t)z * ADIM * EMB;
    const int i = (blockIdx.x * 256 + threadIdx.x) * 4;
    float4 v = *(const float4*)(src + i);
    __half2 a, b;
    a.x = __float2half_rn(v.x); a.y = __float2half_rn(v.y);
    b.x = __float2half_rn(v.z); b.y = __float2half_rn(v.w);
    *(__half2*)(dst + i)     = a;
    *(__half2*)(dst + i + 2) = b;
}

// int8 2-plane quantizer
__device__ __forceinline__ void quant2(float v, char& h8, char& l8) {
    float hq = rintf(v * QINV1);
    hq = fminf(fmaxf(hq, -127.f), 127.f);
    const float r = v - hq * QS1;
    float lq = rintf(r * QINV2);
    lq = fminf(fmaxf(lq, -127.f), 127.f);
    h8 = (char)(int)hq;
    l8 = (char)(int)lq;
}

// ---------------------------------------------------------------------------
// QKV: C = X @ W^T, z slowest.  Q (z==1): 2-term X.  K,V (z==0,2): 1-term.
// Q,K epilogues quantize to int8 planes; V stays fp16 transposed.
// ---------------------------------------------------------------------------
__global__ __launch_bounds__(256, 1) void k_qkv() {
    extern __shared__ char smem[];
    const int bn = blockIdx.x * 256;
    const int bm = blockIdx.y * 128;
    const int z  = blockIdx.z;
    const uint32_t smem_u32 = smem_to_u32(smem);

    float acc[4][8][4] = {};
    const __half* W = g_W + (size_t)z * ADIM * EMB + (size_t)bn * EMB;
    if (z == 1) {
        mma_mainloop<256, 2>(smem_u32,
                             g_Xhi + (size_t)bm * EMB, g_Xlo + (size_t)bm * EMB,
                             EMB, W, EMB, EMB, acc);
    } else {
        mma_mainloop<256, 1>(smem_u32,
                             g_Xhi + (size_t)bm * EMB, nullptr,
                             EMB, W, EMB, EMB, acc);
    }

    const int tid = threadIdx.x, lane = tid & 31, w = tid >> 5;
    const int wm = (w & 1) * 64, wn = (w >> 1) * 64;
    const int gid = lane >> 2, tq = lane & 3;

    if (z == 2) {
        __half* Th = (__half*)smem;           // transpose staging [256][TST]
        #pragma unroll
        for (int mt = 0; mt < 4; ++mt)
            #pragma unroll
            for (int nt = 0; nt < 8; ++nt) {
                const int cl = wn + nt * 8 + tq * 2;
                #pragma unroll
                for (int half = 0; half < 2; ++half) {
                    const int rl = wm + mt * 16 + gid + half * 8;
                    Th[(cl)     * TST + rl] = __float2half_rn(acc[mt][nt][half * 2]);
                    Th[(cl + 1) * TST + rl] = __float2half_rn(acc[mt][nt][half * 2 + 1]);
                }
            }
        __syncthreads();
        const int b = bm >> 11, s0 = bm & 2047;
        const uint4* sh = (const uint4*)(Th + tid * TST);
        uint4* dh = (uint4*)(g_Vt + ((size_t)b << 21) + (size_t)(bn + tid) * SEQ + s0);
        #pragma unroll
        for (int j = 0; j < 16; ++j) dh[j] = sh[j];
    } else {
        char* H8 = smem;                      // [128][QROW]
        char* L8 = smem + 128 * QROW;
        #pragma unroll
        for (int mt = 0; mt < 4; ++mt)
            #pragma unroll
            for (int nt = 0; nt < 8; ++nt) {
                const int cl = wn + nt * 8 + tq * 2;
                #pragma unroll
                for (int half = 0; half < 2; ++half) {
                    const int rl = wm + mt * 16 + gid + half * 8;
                    char h0, l0, h1, l1;
                    quant2(acc[mt][nt][half * 2],     h0, l0);
                    quant2(acc[mt][nt][half * 2 + 1], h1, l1);
                    char2 hp; hp.x = h0; hp.y = h1;
                    char2 lp; lp.x = l0; lp.y = l1;
                    *(char2*)(H8 + rl * QROW + cl) = hp;
                    *(char2*)(L8 + rl * QROW + cl) = lp;
                }
            }
        __syncthreads();
        const int r = tid >> 1, hf = tid & 1;
        const uint4* sh = (const uint4*)(H8 + r * QROW + hf * 128);
        const uint4* sl = (const uint4*)(L8 + r * QROW + hf * 128);
        char* Dh = (z == 0 ? g_Kh8 : g_Qh8) + (size_t)(bm + r) * ADIM + bn + hf * 128;
        char* Dl = (z == 0 ? g_Kl8 : g_Ql8) + (size_t)(bm + r) * ADIM + bn + hf * 128;
        #pragma unroll
        for (int j = 0; j < 8; ++j) ((uint4*)Dh)[j] = sh[j];
        #pragma unroll
        for (int j = 0; j < 8; ++j) ((uint4*)Dl)[j] = sl[j];
    }
}

// ---------------------------------------------------------------------------
// Scores (int8): 128(q) x 128(k) tiles; above-diagonal tiles early-return.
// score = S1^2 * (hh + mid/256) / 32
// ---------------------------------------------------------------------------
__global__ __launch_bounds__(256, 1) void k_scores() {
    const int bk = blockIdx.x * 128;
    const int bq = blockIdx.y * 128;
    const int b  = blockIdx.z;
    if (bk > bq) return;

    extern __shared__ char smem[];
    const uint32_t smem_u32 = smem_to_u32(smem);
    const int tid = threadIdx.x, lane = tid & 31, w = tid >> 5;
    const int wm = (w & 1) * 64, wn = (w >> 1) * 32;

    int hh[4][4][4] = {}, mid[4][4][4] = {};

    const size_t qo = ((size_t)b * SEQ + bq) * ADIM;
    const size_t ko = ((size_t)b * SEQ + bk) * ADIM;
    const char *qh = g_Qh8 + qo, *ql = g_Ql8 + qo;
    const char *kh = g_Kh8 + ko, *kl = g_Kl8 + ko;

    prefetch_s8(smem_u32, 0, 0, qh, ql, kh, kl, tid);
    int st = 0, nst = 1;
    const int nch = ADIM / 128;                        // 8 chunks of 128 bytes
    for (int ch = 0; ch < nch; ++ch) {
        if (ch + 1 < nch) {
            prefetch_s8(smem_u32, nst, (ch + 1) * 128, qh, ql, kh, kl, tid);
            asm volatile("cp.async.wait_group 1;" ::: "memory");
        } else {
            asm volatile("cp.async.wait_group 0;" ::: "memory");
        }
        __syncthreads();
        compute_s8(smem_u32, st, wm, wn, lane, hh, mid);
        st = nst; nst = nst + 1 == 3 ? 0 : nst + 1;
    }

    const float SC = QS1 * QS1 * 0.03125f;             // S1^2 / sqrt(1024)
    const int gid = lane >> 2, tq = lane & 3;
    float* Pb = g_P + (size_t)b * SEQ * SEQ;
    const bool full = (bk < bq);

    #pragma unroll
    for (int mt = 0; mt < 4; ++mt)
        #pragma unroll
        for (int nt = 0; nt < 4; ++nt) {
            const int k = bk + wn + nt * 8 + tq * 2;
            #pragma unroll
            for (int half = 0; half < 2; ++half) {
                const int q = bq + wm + mt * 16 + gid + half * 8;
                const float v0 = ((float)hh[mt][nt][half * 2]
                                  + (float)mid[mt][nt][half * 2] * (1.0f / 256.0f)) * SC;
                const float v1 = ((float)hh[mt][nt][half * 2 + 1]
                                  + (float)mid[mt][nt][half * 2 + 1] * (1.0f / 256.0f)) * SC;
                float* prow = Pb + (size_t)q * SEQ;
                if (full) {
                    *(float2*)(prow + k) = make_float2(v0, v1);
                } else {
                    if (k     <= q) prow[k]     = v0;
                    if (k + 1 <= q) prow[k + 1] = v1;
                }
            }
        }
}

// ---------------------------------------------------------------------------
// Register softmax, vectorized I/O (unchanged from R12).
// ---------------------------------------------------------------------------
__global__ __launch_bounds__(256) void k_softmax() {
    const int row = blockIdx.x;
    const int b = row >> 11, q = row & 2047;
    const size_t off = ((size_t)b * SEQ + q) * SEQ;
    const float* p = g_P + off;
    const int n = q + 1;
    const int kend = (q & ~127) + 128;

    const int tid = threadIdx.x, lane = tid & 31, wid = tid >> 5;
    const int base = tid * 8;
    __shared__ float red[8];

    float v[8];
    if (base + 7 < n) {
        float4 a = *(const float4*)(p + base);
        float4 c = *(const float4*)(p + base + 4);
        v[0] = a.x; v[1] = a.y; v[2] = a.z; v[3] = a.w;
        v[4] = c.x; v[5] = c.y; v[6] = c.z; v[7] = c.w;
    } else {
        #pragma unroll
        for (int e = 0; e < 8; ++e)
            v[e] = (base + e < n) ? p[base + e] : -CUDART_INF_F;
    }

    float m = v[0];
    #pragma unroll
    for (int e = 1; e < 8; ++e) m = fmaxf(m, v[e]);
    #pragma unroll
    for (int o = 16; o > 0; o >>= 1) m = fmaxf(m, __shfl_xor_sync(0xffffffffu, m, o));
    if (lane == 0) red[wid] = m;
    __syncthreads();
    float rowmax = red[0];
    #pragma unroll
    for (int i = 1; i < 8; ++i) rowmax = fmaxf(rowmax, red[i]);
    __syncthreads();

    float s = 0.0f;
    #pragma unroll
    for (int e = 0; e < 8; ++e) {
        const float ex = __expf(v[e] - rowmax);
        v[e] = ex;
        s += ex;
    }
    #pragma unroll
    for (int o = 16; o > 0; o >>= 1) s += __shfl_xor_sync(0xffffffffu, s, o);
    if (lane == 0) red[wid] = s;
    __syncthreads();
    float rowsum = 0.0f;
    #pragma unroll
    for (int i = 0; i < 8; ++i) rowsum += red[i];
    const float inv = 1.0f / rowsum;

    if (base < kend) {
        __half hv[8];
        #pragma unroll
        for (int e = 0; e < 8; ++e)
            hv[e] = __float2half_rn(v[e] * inv);
        *(uint4*)(g_Phi + off + base) = *(const uint4*)hv;
    }
}

// ---------------------------------------------------------------------------
// AV: out = P @ V (via V^T), 128x128 tiles, single-term P, 2 CTAs/SM,
// heavy-first bm order (unchanged from R12).
// ---------------------------------------------------------------------------
__global__ __launch_bounds__(256, 2) void k_av(float* __restrict__ out) {
    const int bn = blockIdx.x * 128;
    const int bm = (gridDim.y - 1 - blockIdx.y) * 128;
    const int b  = blockIdx.z;

    extern __shared__ char smem[];
    const uint32_t smem_u32 = smem_to_u32(smem);

    float acc[4][4][4] = {};
    const size_t po = ((size_t)b * SEQ + bm) * SEQ;
    const size_t vo = ((size_t)b << 21) + (size_t)bn * SEQ;
    mma_mainloop<128, 1>(smem_u32, g_Phi + po, nullptr, SEQ,
                         g_Vt + vo, SEQ, bm + 128, acc);

    const int lane = threadIdx.x & 31, w = threadIdx.x >> 5;
    const int wm = (w & 1) * 64, wn = (w >> 1) * 32;
    const int gid = lane >> 2, tq = lane & 3;

    #pragma unroll
    for (int mt = 0; mt < 4; ++mt)
        #pragma unroll
        for (int nt = 0; nt < 4; ++nt) {
            const int c = bn + wn + nt * 8 + tq * 2;
            #pragma unroll
            for (int half = 0; half < 2; ++half) {
                const int q = bm + wm + mt * 16 + gid + half * 8;
                const float v0 = rintf(acc[mt][nt][half * 2]     * 1.0e4f) * 1.0e-4f;
                const float v1 = rintf(acc[mt][nt][half * 2 + 1] * 1.0e4f) * 1.0e-4f;
                *(float2*)(out + ((size_t)b * SEQ + q) * ADIM + c) = make_float2(v0, v1);
            }
        }
}

// ---------------------------------------------------------------------------
extern "C" void kernel_launch(void* const* d_in, const int* in_sizes, int n_in,
                              void* d_out, int out_size)
{
    const float* X  = (const float*)d_in[0];
    const float* Wk = (const float*)d_in[1];
    const float* Wq = (const float*)d_in[2];
    const float* Wv = (const float*)d_in[3];
    float* out = (float*)d_out;

    cudaFuncSetAttribute(k_qkv,    cudaFuncAttributeMaxDynamicSharedMemorySize, SMEM_BYTES);
    cudaFuncSetAttribute(k_scores, cudaFuncAttributeMaxDynamicSharedMemorySize, SMEM_BYTES);
    cudaFuncSetAttribute(k_av,     cudaFuncAttributeMaxDynamicSharedMemorySize, AV_SMEM);

    k_splitX<<<BSEQ * EMB / 1024, 256>>>(X);
    k_splitW<<<dim3(ADIM * EMB / 1024, 3), 256>>>(Wk, Wq, Wv);

    k_qkv<<<dim3(ADIM / 256, BSEQ / 128, 3), 256, SMEM_BYTES>>>();
    k_scores<<<dim3(SEQ / 128, SEQ / 128, BATCH), 256, SMEM_BYTES>>>();
    k_softmax<<<BSEQ, 256>>>();
    k_av<<<dim3(ADIM / 128, SEQ / 128, BATCH), 256, AV_SMEM>>>(out);
}

// round 14
// speedup vs baseline: 1.8832x; 1.8832x over previous
#include <cuda_runtime.h>
#include <cuda_fp16.h>
#include <math_constants.h>
#include <cstdint>

#define BATCH 4
#define SEQ   2048
#define EMB   1024
#define ADIM  1024
#define BSEQ  (BATCH * SEQ)

// ---------------------------------------------------------------------------
// Scratch (__device__ globals per allocation-free rule)
// ---------------------------------------------------------------------------
__device__ __align__(16) __half g_Xhi[BSEQ * EMB];
__device__ __align__(16) __half g_Xlo[BSEQ * EMB];
__device__ __align__(16) __half g_W  [3 * ADIM * EMB];
__device__ __align__(16) __half g_Qhi[BSEQ * ADIM];
__device__ __align__(16) __half g_Qlo[BSEQ * ADIM];
__device__ __align__(16) __half g_K  [BSEQ * ADIM];
__device__ __align__(16) __half g_Vt [BATCH * ADIM * SEQ];   // V^T [b][a][s]
__device__ __align__(16) float  g_P  [(size_t)BATCH * SEQ * SEQ];
__device__ __align__(16) __half g_Phi[(size_t)BATCH * SEQ * SEQ];

// ---------------------------------------------------------------------------
// PTX helpers (sm_90-safe subset: mma.sync / ldmatrix / cp.async)
// ---------------------------------------------------------------------------
__device__ __forceinline__ uint32_t smem_to_u32(const void* p) {
    uint32_t a;
    asm("{ .reg .u64 t; cvta.to.shared.u64 t, %1; cvt.u32.u64 %0, t; }"
        : "=r"(a) : "l"(p));
    return a;
}

__device__ __forceinline__ void cp16(uint32_t dst, const void* src) {
    asm volatile("cp.async.cg.shared.global [%0], [%1], 16;"
                 :: "r"(dst), "l"(src) : "memory");
}

__device__ __forceinline__ void ldsm_x4(uint32_t (&r)[4], uint32_t addr) {
    asm volatile("ldmatrix.sync.aligned.m8n8.x4.shared.b16 {%0,%1,%2,%3}, [%4];"
                 : "=r"(r[0]), "=r"(r[1]), "=r"(r[2]), "=r"(r[3]) : "r"(addr));
}

__device__ __forceinline__ void mma_f16(float (&c)[4], const uint32_t (&a)[4],
                                        const uint32_t* b) {
    asm volatile(
        "mma.sync.aligned.m16n8k16.row.col.f32.f16.f16.f32 "
        "{%0,%1,%2,%3}, {%4,%5,%6,%7}, {%8,%9}, {%0,%1,%2,%3};"
        : "+f"(c[0]), "+f"(c[1]), "+f"(c[2]), "+f"(c[3])
        : "r"(a[0]), "r"(a[1]), "r"(a[2]), "r"(a[3]), "r"(b[0]), "r"(b[1]));
}

// ---------------------------------------------------------------------------
// Templated GEMM core: CTA 128(M) x CTAN(N), K-chunk 64, 256 threads,
// TERMS = number of A copies (2 = hi/lo split, 1 = single fp16).
// Warp grid 2 x 4: warp tile 64 x (CTAN/4).  3-stage cp.async pipeline.
// ---------------------------------------------------------------------------
#define A_TILE     16384
#define SMEM_BYTES 196608
#define KV_SMEM    98304
#define RST        264            // row-major staging stride (halfs), 256-wide
#define RST2       136            // row-major staging stride (halfs), 128-wide
#define TST        136            // transpose staging stride (halfs)

__device__ __forceinline__ uint32_t sw128(uint32_t off) {
    return off ^ ((off >> 3) & 0x70);
}

template <int CTAN, int TERMS>
__device__ __forceinline__ void prefetch_chunk(
    uint32_t smem_u32, int stage, int kt,
    const __half* __restrict__ a_hi, const __half* __restrict__ a_lo, int lda,
    const __half* __restrict__ b, int ldb, int tid)
{
    constexpr int BOFF  = TERMS * A_TILE;
    constexpr int STAGE = BOFF + CTAN * 128;
    const uint32_t sbase = smem_u32 + stage * STAGE;
    #pragma unroll
    for (int arr = 0; arr < TERMS; ++arr) {
        const __half* src = arr == 0 ? a_hi : a_lo;
        const uint32_t tbase = sbase + arr * A_TILE;
        #pragma unroll
        for (int ii = 0; ii < 4; ++ii) {
            const int rem = ii * 256 + tid;            // [0, 1024)
            const int row = rem >> 3, seg = rem & 7;
            cp16(tbase + sw128((uint32_t)(row * 128 + seg * 16)),
                 src + (size_t)row * lda + kt + seg * 8);
        }
    }
    #pragma unroll
    for (int ii = 0; ii < CTAN / 32; ++ii) {
        const int rem = ii * 256 + tid;                // [0, CTAN*8)
        const int row = rem >> 3, seg = rem & 7;
        cp16(sbase + BOFF + sw128((uint32_t)(row * 128 + seg * 16)),
             b + (size_t)row * ldb + kt + seg * 8);
    }
    asm volatile("cp.async.commit_group;" ::: "memory");
}

template <int CTAN, int TERMS>
__device__ __forceinline__ void compute_chunk(
    uint32_t smem_u32, int stage, int wm, int wn, int lane,
    float acc[4][CTAN / 32][4])
{
    constexpr int BOFF  = TERMS * A_TILE;
    constexpr int STAGE = BOFF + CTAN * 128;
    constexpr int NT = CTAN / 32;
    const uint32_t st = smem_u32 + stage * STAGE;
    #pragma unroll
    for (int ks = 0; ks < 4; ++ks) {
        uint32_t ah[4][4], al[4][4], bh[NT / 2][4];
        #pragma unroll
        for (int mt = 0; mt < 4; ++mt) {
            const int row = wm + mt * 16 + (lane & 15);
            const int byt = ks * 32 + ((lane >> 4) << 4);
            const uint32_t sw = sw128((uint32_t)(row * 128 + byt));
            ldsm_x4(ah[mt], st + sw);
            if constexpr (TERMS == 2) ldsm_x4(al[mt], st + A_TILE + sw);
        }
        #pragma unroll
        for (int p = 0; p < NT / 2; ++p) {
            const int row = wn + p * 16 + ((lane >> 4) << 3) + (lane & 7);
            const int byt = ks * 32 + (((lane >> 3) & 1) << 4);
            ldsm_x4(bh[p], st + BOFF + sw128((uint32_t)(row * 128 + byt)));
        }
        #pragma unroll
        for (int mt = 0; mt < 4; ++mt)
            #pragma unroll
            for (int nt = 0; nt < NT; ++nt)
                mma_f16(acc[mt][nt], ah[mt], &bh[nt >> 1][(nt & 1) * 2]);
        if constexpr (TERMS == 2) {
            #pragma unroll
            for (int mt = 0; mt < 4; ++mt)
                #pragma unroll
                for (int nt = 0; nt < NT; ++nt)
                    mma_f16(acc[mt][nt], al[mt], &bh[nt >> 1][(nt & 1) * 2]);
        }
    }
}

template <int CTAN, int TERMS>
__device__ __forceinline__ void mma_mainloop(
    uint32_t smem_u32,
    const __half* __restrict__ a_hi, const __half* __restrict__ a_lo, int lda,
    const __half* __restrict__ b, int ldb, int klen, float acc[4][CTAN / 32][4])
{
    const int tid = threadIdx.x;
    const int lane = tid & 31, w = tid >> 5;
    const int wm = (w & 1) * 64, wn = (w >> 1) * (CTAN / 4);
    const int nch = klen >> 6;

    prefetch_chunk<CTAN, TERMS>(smem_u32, 0, 0, a_hi, a_lo, lda, b, ldb, tid);

    int st = 0, nst = 1;
    for (int ch = 0; ch < nch; ++ch) {
        if (ch + 1 < nch) {
            prefetch_chunk<CTAN, TERMS>(smem_u32, nst, (ch + 1) << 6,
                                        a_hi, a_lo, lda, b, ldb, tid);
            asm volatile("cp.async.wait_group 1;" ::: "memory");
        } else {
            asm volatile("cp.async.wait_group 0;" ::: "memory");
        }
        __syncthreads();
        compute_chunk<CTAN, TERMS>(smem_u32, st, wm, wn, lane, acc);
        st = nst; nst = nst + 1 == 3 ? 0 : nst + 1;
    }
    __syncthreads();   // epilogue reuses smem
}

// ---------------------------------------------------------------------------
// Splits: X -> fp16 hi/lo;  W -> fp16 single
// ---------------------------------------------------------------------------
__global__ __launch_bounds__(256) void k_splitX(const float* __restrict__ src) {
    const int i = (blockIdx.x * 256 + threadIdx.x) * 4;
    float4 v = *(const float4*)(src + i);
    float vv[4] = {v.x, v.y, v.z, v.w};
    __half h[4], l[4];
    #pragma unroll
    for (int j = 0; j < 4; ++j) {
        h[j] = __float2half_rn(vv[j]);
        l[j] = __float2half_rn(vv[j] - __half2float(h[j]));
    }
    __half2 h01, h23, l01, l23;
    h01.x = h[0]; h01.y = h[1]; h23.x = h[2]; h23.y = h[3];
    l01.x = l[0]; l01.y = l[1]; l23.x = l[2]; l23.y = l[3];
    *(__half2*)(g_Xhi + i)     = h01;
    *(__half2*)(g_Xhi + i + 2) = h23;
    *(__half2*)(g_Xlo + i)     = l01;
    *(__half2*)(g_Xlo + i + 2) = l23;
}

__global__ __launch_bounds__(256) void k_splitW(const float* __restrict__ w0,
                                                const float* __restrict__ w1,
                                                const float* __restrict__ w2) {
    const int z = blockIdx.y;
    const float* src = z == 0 ? w0 : z == 1 ? w1 : w2;
    __half* dst = g_W + (size_t)z * ADIM * EMB;
    const int i = (blockIdx.x * 256 + threadIdx.x) * 4;
    float4 v = *(const float4*)(src + i);
    __half2 a, b;
    a.x = __float2half_rn(v.x); a.y = __float2half_rn(v.y);
    b.x = __float2half_rn(v.z); b.y = __float2half_rn(v.w);
    *(__half2*)(dst + i)     = a;
    *(__half2*)(dst + i + 2) = b;
}

// ---------------------------------------------------------------------------
// Q projection: Q = X @ Wq^T, 2-term X, 128x256 tile, 1 CTA/SM.
// Writes Q as fp16 hi/lo.
// ---------------------------------------------------------------------------
__global__ __launch_bounds__(256, 1) void k_q() {
    extern __shared__ char smem[];
    const int bn = blockIdx.x * 256;
    const int bm = blockIdx.y * 128;
    const uint32_t smem_u32 = smem_to_u32(smem);

    float acc[4][8][4] = {};
    const __half* W = g_W + (size_t)ADIM * EMB + (size_t)bn * EMB;   // z=1
    mma_mainloop<256, 2>(smem_u32,
                         g_Xhi + (size_t)bm * EMB, g_Xlo + (size_t)bm * EMB,
                         EMB, W, EMB, EMB, acc);

    const int tid = threadIdx.x, lane = tid & 31, w = tid >> 5;
    const int wm = (w & 1) * 64, wn = (w >> 1) * 64;
    const int gid = lane >> 2, tq = lane & 3;

    __half* Th = (__half*)smem;               // [128][RST]
    __half* Tl = Th + 128 * RST;

    #pragma unroll
    for (int mt = 0; mt < 4; ++mt)
        #pragma unroll
        for (int nt = 0; nt < 8; ++nt) {
            const int cl = wn + nt * 8 + tq * 2;
            #pragma unroll
            for (int half = 0; half < 2; ++half) {
                const int rl = wm + mt * 16 + gid + half * 8;
                const float v0 = acc[mt][nt][half * 2];
                const float v1 = acc[mt][nt][half * 2 + 1];
                const __half h0 = __float2half_rn(v0), h1 = __float2half_rn(v1);
                __half2 hh, ll;
                hh.x = h0; hh.y = h1;
                ll.x = __float2half_rn(v0 - __half2float(h0));
                ll.y = __float2half_rn(v1 - __half2float(h1));
                *(__half2*)(Th + rl * RST + cl) = hh;
                *(__half2*)(Tl + rl * RST + cl) = ll;
            }
        }
    __syncthreads();

    const int r = tid >> 1, hf = tid & 1;
    const uint4* sh = (const uint4*)(Th + r * RST + hf * 128);
    const uint4* sl = (const uint4*)(Tl + r * RST + hf * 128);
    uint4* dh = (uint4*)(g_Qhi + (size_t)(bm + r) * ADIM + bn + hf * 128);
    uint4* dl = (uint4*)(g_Qlo + (size_t)(bm + r) * ADIM + bn + hf * 128);
    #pragma unroll
    for (int j = 0; j < 16; ++j) dh[j] = sh[j];
    #pragma unroll
    for (int j = 0; j < 16; ++j) dl[j] = sl[j];
}

// ---------------------------------------------------------------------------
// K / V projections: 1-term X, 128x128 tile, 96KB smem, 2 CTAs/SM.
// z = blockIdx.z: 0 -> K (fp16 row-major), 1 -> V (fp16 transposed).
// ---------------------------------------------------------------------------
__global__ __launch_bounds__(256, 2) void k_kv() {
    extern __shared__ char smem[];
    const int bn = blockIdx.x * 128;
    const int bm = blockIdx.y * 128;
    const int z  = blockIdx.z;                // 0 = K, 1 = V
    const uint32_t smem_u32 = smem_to_u32(smem);

    float acc[4][4][4] = {};
    const __half* W = g_W + (size_t)(z == 0 ? 0 : 2) * ADIM * EMB + (size_t)bn * EMB;
    mma_mainloop<128, 1>(smem_u32,
                         g_Xhi + (size_t)bm * EMB, nullptr,
                         EMB, W, EMB, EMB, acc);

    const int tid = threadIdx.x, lane = tid & 31, w = tid >> 5;
    const int wm = (w & 1) * 64, wn = (w >> 1) * 32;
    const int gid = lane >> 2, tq = lane & 3;

    __half* Th = (__half*)smem;               // [128][136] either orientation

    #pragma unroll
    for (int mt = 0; mt < 4; ++mt)
        #pragma unroll
        for (int nt = 0; nt < 4; ++nt) {
            const int cl = wn + nt * 8 + tq * 2;
            #pragma unroll
            for (int half = 0; half < 2; ++half) {
                const int rl = wm + mt * 16 + gid + half * 8;
                const __half h0 = __float2half_rn(acc[mt][nt][half * 2]);
                const __half h1 = __float2half_rn(acc[mt][nt][half * 2 + 1]);
                if (z == 1) {                 // transpose: T[a][s]
                    Th[(cl)     * TST + rl] = h0;
                    Th[(cl + 1) * TST + rl] = h1;
                } else {                      // row-major: T[s][a]
                    __half2 hh; hh.x = h0; hh.y = h1;
                    *(__half2*)(Th + rl * RST2 + cl) = hh;
                }
            }
        }
    __syncthreads();

    const int r = tid >> 1, hf = tid & 1;     // 64 halfs each = 8 uint4
    if (z == 1) {
        const int b = bm >> 11, s0 = bm & 2047;
        const uint4* sh = (const uint4*)(Th + r * TST + hf * 64);
        uint4* dh = (uint4*)(g_Vt + ((size_t)b << 21) + (size_t)(bn + r) * SEQ + s0 + hf * 64);
        #pragma unroll
        for (int j = 0; j < 8; ++j) dh[j] = sh[j];
    } else {
        const uint4* sh = (const uint4*)(Th + r * RST2 + hf * 64);
        uint4* dh = (uint4*)(g_K + (size_t)(bm + r) * ADIM + bn + hf * 64);
        #pragma unroll
        for (int j = 0; j < 8; ++j) dh[j] = sh[j];
    }
}

// ---------------------------------------------------------------------------
// Scores: 128(q) x 256(k) tiles, 2-term; above-diagonal tiles early-return.
// ---------------------------------------------------------------------------
__global__ __launch_bounds__(256, 1) void k_scores() {
    const int bk = blockIdx.x * 256;
    const int bq = blockIdx.y * 128;
    const int b  = blockIdx.z;
    if (bk > bq + 127) return;

    extern __shared__ char smem[];
    const uint32_t smem_u32 = smem_to_u32(smem);

    float acc[4][8][4] = {};
    const size_t qo = ((size_t)b * SEQ + bq) * ADIM;
    const size_t ko = ((size_t)b * SEQ + bk) * ADIM;
    mma_mainloop<256, 2>(smem_u32, g_Qhi + qo, g_Qlo + qo, ADIM,
                         g_K + ko, ADIM, ADIM, acc);

    const float scale = 0.03125f;  // 1/sqrt(1024)
    const int lane = threadIdx.x & 31, w = threadIdx.x >> 5;
    const int wm = (w & 1) * 64, wn = (w >> 1) * 64;
    const int gid = lane >> 2, tq = lane & 3;
    float* Pb = g_P + (size_t)b * SEQ * SEQ;
    const bool full = (bk + 255 <= bq);

    #pragma unroll
    for (int mt = 0; mt < 4; ++mt)
        #pragma unroll
        for (int nt = 0; nt < 8; ++nt) {
            const int k = bk + wn + nt * 8 + tq * 2;
            #pragma unroll
            for (int half = 0; half < 2; ++half) {
                const int q = bq + wm + mt * 16 + gid + half * 8;
                const float v0 = acc[mt][nt][half * 2] * scale;
                const float v1 = acc[mt][nt][half * 2 + 1] * scale;
                float* prow = Pb + (size_t)q * SEQ;
                if (full) {
                    *(float2*)(prow + k) = make_float2(v0, v1);
                } else {
                    if (k     <= q) prow[k]     = v0;
                    if (k + 1 <= q) prow[k + 1] = v1;
                }
            }
        }
}

// ---------------------------------------------------------------------------
// Register softmax, vectorized I/O.
// ---------------------------------------------------------------------------
__global__ __launch_bounds__(256) void k_softmax() {
    const int row = blockIdx.x;
    const int b = row >> 11, q = row & 2047;
    const size_t off = ((size_t)b * SEQ + q) * SEQ;
    const float* p = g_P + off;
    const int n = q + 1;
    const int kend = (q & ~127) + 128;

    const int tid = threadIdx.x, lane = tid & 31, wid = tid >> 5;
    const int base = tid * 8;
    __shared__ float red[8];

    float v[8];
    if (base + 7 < n) {
        float4 a = *(const float4*)(p + base);
        float4 c = *(const float4*)(p + base + 4);
        v[0] = a.x; v[1] = a.y; v[2] = a.z; v[3] = a.w;
        v[4] = c.x; v[5] = c.y; v[6] = c.z; v[7] = c.w;
    } else {
        #pragma unroll
        for (int e = 0; e < 8; ++e)
            v[e] = (base + e < n) ? p[base + e] : -CUDART_INF_F;
    }

    float m = v[0];
    #pragma unroll
    for (int e = 1; e < 8; ++e) m = fmaxf(m, v[e]);
    #pragma unroll
    for (int o = 16; o > 0; o >>= 1) m = fmaxf(m, __shfl_xor_sync(0xffffffffu, m, o));
    if (lane == 0) red[wid] = m;
    __syncthreads();
    float rowmax = red[0];
    #pragma unroll
    for (int i = 1; i < 8; ++i) rowmax = fmaxf(rowmax, red[i]);
    __syncthreads();

    float s = 0.0f;
    #pragma unroll
    for (int e = 0; e < 8; ++e) {
        const float ex = __expf(v[e] - rowmax);
        v[e] = ex;
        s += ex;
    }
    #pragma unroll
    for (int o = 16; o > 0; o >>= 1) s += __shfl_xor_sync(0xffffffffu, s, o);
    if (lane == 0) red[wid] = s;
    __syncthreads();
    float rowsum = 0.0f;
    #pragma unroll
    for (int i = 0; i < 8; ++i) rowsum += red[i];
    const float inv = 1.0f / rowsum;

    if (base < kend) {
        __half hv[8];
        #pragma unroll
        for (int e = 0; e < 8; ++e)
            hv[e] = __float2half_rn(v[e] * inv);
        *(uint4*)(g_Phi + off + base) = *(const uint4*)hv;
    }
}

// ---------------------------------------------------------------------------
// AV: out = P @ V (via V^T), 128x128 tiles, single-term P, 2 CTAs/SM,
// heavy-first bm order.
// ---------------------------------------------------------------------------
__global__ __launch_bounds__(256, 2) void k_av(float* __restrict__ out) {
    const int bn = blockIdx.x * 128;
    const int bm = (gridDim.y - 1 - blockIdx.y) * 128;
    const int b  = blockIdx.z;

    extern __shared__ char smem[];
    const uint32_t smem_u32 = smem_to_u32(smem);

    float acc[4][4][4] = {};
    const size_t po = ((size_t)b * SEQ + bm) * SEQ;
    const size_t vo = ((size_t)b << 21) + (size_t)bn * SEQ;
    mma_mainloop<128, 1>(smem_u32, g_Phi + po, nullptr, SEQ,
                         g_Vt + vo, SEQ, bm + 128, acc);

    const int lane = threadIdx.x & 31, w = threadIdx.x >> 5;
    const int wm = (w & 1) * 64, wn = (w >> 1) * 32;
    const int gid = lane >> 2, tq = lane & 3;

    #pragma unroll
    for (int mt = 0; mt < 4; ++mt)
        #pragma unroll
        for (int nt = 0; nt < 4; ++nt) {
            const int c = bn + wn + nt * 8 + tq * 2;
            #pragma unroll
            for (int half = 0; half < 2; ++half) {
                const int q = bm + wm + mt * 16 + gid + half * 8;
                const float v0 = rintf(acc[mt][nt][half * 2]     * 1.0e4f) * 1.0e-4f;
                const float v1 = rintf(acc[mt][nt][half * 2 + 1] * 1.0e4f) * 1.0e-4f;
                *(float2*)(out + ((size_t)b * SEQ + q) * ADIM + c) = make_float2(v0, v1);
            }
        }
}

// ---------------------------------------------------------------------------
extern "C" void kernel_launch(void* const* d_in, const int* in_sizes, int n_in,
                              void* d_out, int out_size)
{
    const float* X  = (const float*)d_in[0];
    const float* Wk = (const float*)d_in[1];
    const float* Wq = (const float*)d_in[2];
    const float* Wv = (const float*)d_in[3];
    float* out = (float*)d_out;

    cudaFuncSetAttribute(k_q,      cudaFuncAttributeMaxDynamicSharedMemorySize, SMEM_BYTES);
    cudaFuncSetAttribute(k_kv,     cudaFuncAttributeMaxDynamicSharedMemorySize, KV_SMEM);
    cudaFuncSetAttribute(k_scores, cudaFuncAttributeMaxDynamicSharedMemorySize, SMEM_BYTES);
    cudaFuncSetAttribute(k_av,     cudaFuncAttributeMaxDynamicSharedMemorySize, KV_SMEM);

    k_splitX<<<BSEQ * EMB / 1024, 256>>>(X);
    k_splitW<<<dim3(ADIM * EMB / 1024, 3), 256>>>(Wk, Wq, Wv);

    k_kv<<<dim3(ADIM / 128, BSEQ / 128, 2), 256, KV_SMEM>>>();
    k_q <<<dim3(ADIM / 256, BSEQ / 128),    256, SMEM_BYTES>>>();
    k_scores<<<dim3(SEQ / 256, SEQ / 128, BATCH), 256, SMEM_BYTES>>>();
    k_softmax<<<BSEQ, 256>>>();
    k_av<<<dim3(ADIM / 128, SEQ / 128, BATCH), 256, KV_SMEM>>>(out);
}

// round 15
// speedup vs baseline: 2.1530x; 1.1433x over previous
#include <cuda_runtime.h>
#include <cuda_fp16.h>
#include <math_constants.h>
#include <cstdint>

#define BATCH 4
#define SEQ   2048
#define EMB   1024
#define ADIM  1024
#define BSEQ  (BATCH * SEQ)

// ---------------------------------------------------------------------------
// Scratch (__device__ globals per allocation-free rule)
// ---------------------------------------------------------------------------
__device__ __align__(16) __half g_Xhi[BSEQ * EMB];
__device__ __align__(16) __half g_W  [3 * ADIM * EMB];
__device__ __align__(16) __half g_Qhi[BSEQ * ADIM];
__device__ __align__(16) __half g_Qlo[BSEQ * ADIM];
__device__ __align__(16) __half g_K  [BSEQ * ADIM];
__device__ __align__(16) __half g_Vt [BATCH * ADIM * SEQ];   // V^T [b][a][s]
__device__ __align__(16) float  g_P  [(size_t)BATCH * SEQ * SEQ];
__device__ __align__(16) __half g_Phi[(size_t)BATCH * SEQ * SEQ];

// ---------------------------------------------------------------------------
// PTX helpers (sm_90-safe subset: mma.sync / ldmatrix / cp.async)
// ---------------------------------------------------------------------------
__device__ __forceinline__ uint32_t smem_to_u32(const void* p) {
    uint32_t a;
    asm("{ .reg .u64 t; cvta.to.shared.u64 t, %1; cvt.u32.u64 %0, t; }"
        : "=r"(a) : "l"(p));
    return a;
}

__device__ __forceinline__ void cp16(uint32_t dst, const void* src) {
    asm volatile("cp.async.cg.shared.global [%0], [%1], 16;"
                 :: "r"(dst), "l"(src) : "memory");
}

__device__ __forceinline__ void ldsm_x4(uint32_t (&r)[4], uint32_t addr) {
    asm volatile("ldmatrix.sync.aligned.m8n8.x4.shared.b16 {%0,%1,%2,%3}, [%4];"
                 : "=r"(r[0]), "=r"(r[1]), "=r"(r[2]), "=r"(r[3]) : "r"(addr));
}

__device__ __forceinline__ void mma_f16(float (&c)[4], const uint32_t (&a)[4],
                                        const uint32_t* b) {
    asm volatile(
        "mma.sync.aligned.m16n8k16.row.col.f32.f16.f16.f32 "
        "{%0,%1,%2,%3}, {%4,%5,%6,%7}, {%8,%9}, {%0,%1,%2,%3};"
        : "+f"(c[0]), "+f"(c[1]), "+f"(c[2]), "+f"(c[3])
        : "r"(a[0]), "r"(a[1]), "r"(a[2]), "r"(a[3]), "r"(b[0]), "r"(b[1]));
}

// ---------------------------------------------------------------------------
// Templated GEMM core: CTA 128(M) x CTAN(N), K-chunk 64, 256 threads,
// TERMS = number of A copies (2 = hi/lo split, 1 = single fp16).
// Warp grid 2 x 4: warp tile 64 x (CTAN/4).  3-stage cp.async pipeline.
// ---------------------------------------------------------------------------
#define A_TILE     16384
#define SMEM_BYTES 196608
#define SM96       98304
#define RST        264            // row-major staging stride (halfs), 256-wide
#define RST2       136            // row-major staging stride (halfs), 128-wide
#define TST        136            // transpose staging stride (halfs)

__device__ __forceinline__ uint32_t sw128(uint32_t off) {
    return off ^ ((off >> 3) & 0x70);
}

template <int CTAN, int TERMS>
__device__ __forceinline__ void prefetch_chunk(
    uint32_t smem_u32, int stage, int kt,
    const __half* __restrict__ a_hi, const __half* __restrict__ a_lo, int lda,
    const __half* __restrict__ b, int ldb, int tid)
{
    constexpr int BOFF  = TERMS * A_TILE;
    constexpr int STAGE = BOFF + CTAN * 128;
    const uint32_t sbase = smem_u32 + stage * STAGE;
    #pragma unroll
    for (int arr = 0; arr < TERMS; ++arr) {
        const __half* src = arr == 0 ? a_hi : a_lo;
        const uint32_t tbase = sbase + arr * A_TILE;
        #pragma unroll
        for (int ii = 0; ii < 4; ++ii) {
            const int rem = ii * 256 + tid;            // [0, 1024)
            const int row = rem >> 3, seg = rem & 7;
            cp16(tbase + sw128((uint32_t)(row * 128 + seg * 16)),
                 src + (size_t)row * lda + kt + seg * 8);
        }
    }
    #pragma unroll
    for (int ii = 0; ii < CTAN / 32; ++ii) {
        const int rem = ii * 256 + tid;                // [0, CTAN*8)
        const int row = rem >> 3, seg = rem & 7;
        cp16(sbase + BOFF + sw128((uint32_t)(row * 128 + seg * 16)),
             b + (size_t)row * ldb + kt + seg * 8);
    }
    asm volatile("cp.async.commit_group;" ::: "memory");
}

template <int CTAN, int TERMS>
__device__ __forceinline__ void compute_chunk(
    uint32_t smem_u32, int stage, int wm, int wn, int lane,
    float acc[4][CTAN / 32][4])
{
    constexpr int BOFF  = TERMS * A_TILE;
    constexpr int STAGE = BOFF + CTAN * 128;
    constexpr int NT = CTAN / 32;
    const uint32_t st = smem_u32 + stage * STAGE;
    #pragma unroll
    for (int ks = 0; ks < 4; ++ks) {
        uint32_t ah[4][4], al[4][4], bh[NT / 2][4];
        #pragma unroll
        for (int mt = 0; mt < 4; ++mt) {
            const int row = wm + mt * 16 + (lane & 15);
            const int byt = ks * 32 + ((lane >> 4) << 4);
            const uint32_t sw = sw128((uint32_t)(row * 128 + byt));
            ldsm_x4(ah[mt], st + sw);
            if constexpr (TERMS == 2) ldsm_x4(al[mt], st + A_TILE + sw);
        }
        #pragma unroll
        for (int p = 0; p < NT / 2; ++p) {
            const int row = wn + p * 16 + ((lane >> 4) << 3) + (lane & 7);
            const int byt = ks * 32 + (((lane >> 3) & 1) << 4);
            ldsm_x4(bh[p], st + BOFF + sw128((uint32_t)(row * 128 + byt)));
        }
        #pragma unroll
        for (int mt = 0; mt < 4; ++mt)
            #pragma unroll
            for (int nt = 0; nt < NT; ++nt)
                mma_f16(acc[mt][nt], ah[mt], &bh[nt >> 1][(nt & 1) * 2]);
        if constexpr (TERMS == 2) {
            #pragma unroll
            for (int mt = 0; mt < 4; ++mt)
                #pragma unroll
                for (int nt = 0; nt < NT; ++nt)
                    mma_f16(acc[mt][nt], al[mt], &bh[nt >> 1][(nt & 1) * 2]);
        }
    }
}

template <int CTAN, int TERMS>
__device__ __forceinline__ void mma_mainloop(
    uint32_t smem_u32,
    const __half* __restrict__ a_hi, const __half* __restrict__ a_lo, int lda,
    const __half* __restrict__ b, int ldb, int klen, float acc[4][CTAN / 32][4])
{
    const int tid = threadIdx.x;
    const int lane = tid & 31, w = tid >> 5;
    const int wm = (w & 1) * 64, wn = (w >> 1) * (CTAN / 4);
    const int nch = klen >> 6;

    prefetch_chunk<CTAN, TERMS>(smem_u32, 0, 0, a_hi, a_lo, lda, b, ldb, tid);

    int st = 0, nst = 1;
    for (int ch = 0; ch < nch; ++ch) {
        if (ch + 1 < nch) {
            prefetch_chunk<CTAN, TERMS>(smem_u32, nst, (ch + 1) << 6,
                                        a_hi, a_lo, lda, b, ldb, tid);
            asm volatile("cp.async.wait_group 1;" ::: "memory");
        } else {
            asm volatile("cp.async.wait_group 0;" ::: "memory");
        }
        __syncthreads();
        compute_chunk<CTAN, TERMS>(smem_u32, st, wm, wn, lane, acc);
        st = nst; nst = nst + 1 == 3 ? 0 : nst + 1;
    }
    __syncthreads();   // epilogue reuses smem
}

// ---------------------------------------------------------------------------
// Splits: X -> fp16 (single);  W -> fp16 single
// ---------------------------------------------------------------------------
__global__ __launch_bounds__(256) void k_splitX(const float* __restrict__ src) {
    const int i = (blockIdx.x * 256 + threadIdx.x) * 4;
    float4 v = *(const float4*)(src + i);
    __half2 a, b;
    a.x = __float2half_rn(v.x); a.y = __float2half_rn(v.y);
    b.x = __float2half_rn(v.z); b.y = __float2half_rn(v.w);
    *(__half2*)(g_Xhi + i)     = a;
    *(__half2*)(g_Xhi + i + 2) = b;
}

__global__ __launch_bounds__(256) void k_splitW(const float* __restrict__ w0,
                                                const float* __restrict__ w1,
                                                const float* __restrict__ w2) {
    const int z = blockIdx.y;
    const float* src = z == 0 ? w0 : z == 1 ? w1 : w2;
    __half* dst = g_W + (size_t)z * ADIM * EMB;
    const int i = (blockIdx.x * 256 + threadIdx.x) * 4;
    float4 v = *(const float4*)(src + i);
    __half2 a, b;
    a.x = __float2half_rn(v.x); a.y = __float2half_rn(v.y);
    b.x = __float2half_rn(v.z); b.y = __float2half_rn(v.w);
    *(__half2*)(dst + i)     = a;
    *(__half2*)(dst + i + 2) = b;
}

// ---------------------------------------------------------------------------
// QKV projections, all 1-term X: CTA 128x128, 96KB smem, 2 CTAs/SM.
// z = blockIdx.z: 0 -> K (fp16), 1 -> Q (fp16 hi/lo split of result),
//                 2 -> V (fp16 transposed).  1536 CTAs = 5.19 waves.
// ---------------------------------------------------------------------------
__global__ __launch_bounds__(256, 2) void k_qkv() {
    extern __shared__ char smem[];
    const int bn = blockIdx.x * 128;
    const int bm = blockIdx.y * 128;
    const int z  = blockIdx.z;
    const uint32_t smem_u32 = smem_to_u32(smem);

    float acc[4][4][4] = {};
    const __half* W = g_W + (size_t)z * ADIM * EMB + (size_t)bn * EMB;
    mma_mainloop<128, 1>(smem_u32,
                         g_Xhi + (size_t)bm * EMB, nullptr,
                         EMB, W, EMB, EMB, acc);

    const int tid = threadIdx.x, lane = tid & 31, w = tid >> 5;
    const int wm = (w & 1) * 64, wn = (w >> 1) * 32;
    const int gid = lane >> 2, tq = lane & 3;

    __half* Th = (__half*)smem;               // [128][136]
    __half* Tl = Th + 128 * RST2;             // Q only

    #pragma unroll
    for (int mt = 0; mt < 4; ++mt)
        #pragma unroll
        for (int nt = 0; nt < 4; ++nt) {
            const int cl = wn + nt * 8 + tq * 2;
            #pragma unroll
            for (int half = 0; half < 2; ++half) {
                const int rl = wm + mt * 16 + gid + half * 8;
                const float v0 = acc[mt][nt][half * 2];
                const float v1 = acc[mt][nt][half * 2 + 1];
                const __half h0 = __float2half_rn(v0), h1 = __float2half_rn(v1);
                if (z == 2) {                 // transpose: T[a][s]
                    Th[(cl)     * TST + rl] = h0;
                    Th[(cl + 1) * TST + rl] = h1;
                } else {
                    __half2 hh; hh.x = h0; hh.y = h1;
                    *(__half2*)(Th + rl * RST2 + cl) = hh;
                    if (z == 1) {             // Q: lo = residual of fp16 round
                        __half2 ll;
                        ll.x = __float2half_rn(v0 - __half2float(h0));
                        ll.y = __float2half_rn(v1 - __half2float(h1));
                        *(__half2*)(Tl + rl * RST2 + cl) = ll;
                    }
                }
            }
        }
    __syncthreads();

    const int r = tid >> 1, hf = tid & 1;     // 64 halfs each = 8 uint4
    if (z == 2) {
        const int b = bm >> 11, s0 = bm & 2047;
        const uint4* sh = (const uint4*)(Th + r * TST + hf * 64);
        uint4* dh = (uint4*)(g_Vt + ((size_t)b << 21) + (size_t)(bn + r) * SEQ + s0 + hf * 64);
        #pragma unroll
        for (int j = 0; j < 8; ++j) dh[j] = sh[j];
    } else if (z == 0) {
        const uint4* sh = (const uint4*)(Th + r * RST2 + hf * 64);
        uint4* dh = (uint4*)(g_K + (size_t)(bm + r) * ADIM + bn + hf * 64);
        #pragma unroll
        for (int j = 0; j < 8; ++j) dh[j] = sh[j];
    } else {
        const uint4* sh = (const uint4*)(Th + r * RST2 + hf * 64);
        const uint4* sl = (const uint4*)(Tl + r * RST2 + hf * 64);
        uint4* dh = (uint4*)(g_Qhi + (size_t)(bm + r) * ADIM + bn + hf * 64);
        uint4* dl = (uint4*)(g_Qlo + (size_t)(bm + r) * ADIM + bn + hf * 64);
        #pragma unroll
        for (int j = 0; j < 8; ++j) dh[j] = sh[j];
        #pragma unroll
        for (int j = 0; j < 8; ++j) dl[j] = sl[j];
    }
}

// ---------------------------------------------------------------------------
// Scores: 128(q) x 256(k) tiles, 2-term Q; above-diagonal tiles early-return.
// ---------------------------------------------------------------------------
__global__ __launch_bounds__(256, 1) void k_scores() {
    const int bk = blockIdx.x * 256;
    const int bq = blockIdx.y * 128;
    const int b  = blockIdx.z;
    if (bk > bq + 127) return;

    extern __shared__ char smem[];
    const uint32_t smem_u32 = smem_to_u32(smem);

    float acc[4][8][4] = {};
    const size_t qo = ((size_t)b * SEQ + bq) * ADIM;
    const size_t ko = ((size_t)b * SEQ + bk) * ADIM;
    mma_mainloop<256, 2>(smem_u32, g_Qhi + qo, g_Qlo + qo, ADIM,
                         g_K + ko, ADIM, ADIM, acc);

    const float scale = 0.03125f;  // 1/sqrt(1024)
    const int lane = threadIdx.x & 31, w = threadIdx.x >> 5;
    const int wm = (w & 1) * 64, wn = (w >> 1) * 64;
    const int gid = lane >> 2, tq = lane & 3;
    float* Pb = g_P + (size_t)b * SEQ * SEQ;
    const bool full = (bk + 255 <= bq);

    #pragma unroll
    for (int mt = 0; mt < 4; ++mt)
        #pragma unroll
        for (int nt = 0; nt < 8; ++nt) {
            const int k = bk + wn + nt * 8 + tq * 2;
            #pragma unroll
            for (int half = 0; half < 2; ++half) {
                const int q = bq + wm + mt * 16 + gid + half * 8;
                const float v0 = acc[mt][nt][half * 2] * scale;
                const float v1 = acc[mt][nt][half * 2 + 1] * scale;
                float* prow = Pb + (size_t)q * SEQ;
                if (full) {
                    *(float2*)(prow + k) = make_float2(v0, v1);
                } else {
                    if (k     <= q) prow[k]     = v0;
                    if (k + 1 <= q) prow[k + 1] = v1;
                }
            }
        }
}

// ---------------------------------------------------------------------------
// Register softmax, vectorized I/O.
// ---------------------------------------------------------------------------
__global__ __launch_bounds__(256) void k_softmax() {
    const int row = blockIdx.x;
    const int b = row >> 11, q = row & 2047;
    const size_t off = ((size_t)b * SEQ + q) * SEQ;
    const float* p = g_P + off;
    const int n = q + 1;
    const int kend = (q & ~127) + 128;

    const int tid = threadIdx.x, lane = tid & 31, wid = tid >> 5;
    const int base = tid * 8;
    __shared__ float red[8];

    float v[8];
    if (base + 7 < n) {
        float4 a = *(const float4*)(p + base);
        float4 c = *(const float4*)(p + base + 4);
        v[0] = a.x; v[1] = a.y; v[2] = a.z; v[3] = a.w;
        v[4] = c.x; v[5] = c.y; v[6] = c.z; v[7] = c.w;
    } else {
        #pragma unroll
        for (int e = 0; e < 8; ++e)
            v[e] = (base + e < n) ? p[base + e] : -CUDART_INF_F;
    }

    float m = v[0];
    #pragma unroll
    for (int e = 1; e < 8; ++e) m = fmaxf(m, v[e]);
    #pragma unroll
    for (int o = 16; o > 0; o >>= 1) m = fmaxf(m, __shfl_xor_sync(0xffffffffu, m, o));
    if (lane == 0) red[wid] = m;
    __syncthreads();
    float rowmax = red[0];
    #pragma unroll
    for (int i = 1; i < 8; ++i) rowmax = fmaxf(rowmax, red[i]);
    __syncthreads();

    float s = 0.0f;
    #pragma unroll
    for (int e = 0; e < 8; ++e) {
        const float ex = __expf(v[e] - rowmax);
        v[e] = ex;
        s += ex;
    }
    #pragma unroll
    for (int o = 16; o > 0; o >>= 1) s += __shfl_xor_sync(0xffffffffu, s, o);
    if (lane == 0) red[wid] = s;
    __syncthreads();
    float rowsum = 0.0f;
    #pragma unroll
    for (int i = 0; i < 8; ++i) rowsum += red[i];
    const float inv = 1.0f / rowsum;

    if (base < kend) {
        __half hv[8];
        #pragma unroll
        for (int e = 0; e < 8; ++e)
            hv[e] = __float2half_rn(v[e] * inv);
        *(uint4*)(g_Phi + off + base) = *(const uint4*)hv;
    }
}

// ---------------------------------------------------------------------------
// AV: out = P @ V (via V^T), 128x128 tiles, single-term P, 2 CTAs/SM,
// heavy-first bm order.
// ---------------------------------------------------------------------------
__global__ __launch_bounds__(256, 2) void k_av(float* __restrict__ out) {
    const int bn = blockIdx.x * 128;
    const int bm = (gridDim.y - 1 - blockIdx.y) * 128;
    const int b  = blockIdx.z;

    extern __shared__ char smem[];
    const uint32_t smem_u32 = smem_to_u32(smem);

    float acc[4][4][4] = {};
    const size_t po = ((size_t)b * SEQ + bm) * SEQ;
    const size_t vo = ((size_t)b << 21) + (size_t)bn * SEQ;
    mma_mainloop<128, 1>(smem_u32, g_Phi + po, nullptr, SEQ,
                         g_Vt + vo, SEQ, bm + 128, acc);

    const int lane = threadIdx.x & 31, w = threadIdx.x >> 5;
    const int wm = (w & 1) * 64, wn = (w >> 1) * 32;
    const int gid = lane >> 2, tq = lane & 3;

    #pragma unroll
    for (int mt = 0; mt < 4; ++mt)
        #pragma unroll
        for (int nt = 0; nt < 4; ++nt) {
            const int c = bn + wn + nt * 8 + tq * 2;
            #pragma unroll
            for (int half = 0; half < 2; ++half) {
                const int q = bm + wm + mt * 16 + gid + half * 8;
                const float v0 = rintf(acc[mt][nt][half * 2]     * 1.0e4f) * 1.0e-4f;
                const float v1 = rintf(acc[mt][nt][half * 2 + 1] * 1.0e4f) * 1.0e-4f;
                *(float2*)(out + ((size_t)b * SEQ + q) * ADIM + c) = make_float2(v0, v1);
            }
        }
}

// ---------------------------------------------------------------------------
extern "C" void kernel_launch(void* const* d_in, const int* in_sizes, int n_in,
                              void* d_out, int out_size)
{
    const float* X  = (const float*)d_in[0];
    const float* Wk = (const float*)d_in[1];
    const float* Wq = (const float*)d_in[2];
    const float* Wv = (const float*)d_in[3];
    float* out = (float*)d_out;

    cudaFuncSetAttribute(k_qkv,    cudaFuncAttributeMaxDynamicSharedMemorySize, SM96);
    cudaFuncSetAttribute(k_scores, cudaFuncAttributeMaxDynamicSharedMemorySize, SMEM_BYTES);
    cudaFuncSetAttribute(k_av,     cudaFuncAttributeMaxDynamicSharedMemorySize, SM96);

    k_splitX<<<BSEQ * EMB / 1024, 256>>>(X);
    k_splitW<<<dim3(ADIM * EMB / 1024, 3), 256>>>(Wk, Wq, Wv);

    k_qkv<<<dim3(ADIM / 128, BSEQ / 128, 3), 256, SM96>>>();
    k_scores<<<dim3(SEQ / 256, SEQ / 128, BATCH), 256, SMEM_BYTES>>>();
    k_softmax<<<BSEQ, 256>>>();
    k_av<<<dim3(ADIM / 128, SEQ / 128, BATCH), 256, SM96>>>(out);
}